// round 6
// baseline (speedup 1.0000x reference)
#include <cuda_runtime.h>
#include <cuda_bf16.h>
#include <math_constants.h>

// ---------------------------------------------------------------------------
// GAT layer: out = relu( segment_softmax_aggregate( leaky_relu(a_s[j]+a_d[i]),
//                                                   h[j] ) + bias )
// h = x @ W, self loops added, softmax over incoming edges per dst node.
//
// Pipeline (stream-ordered, graph-capturable, allocation-free):
//   0. detect      edge_index dtype sniff (int32 vs int64) -> g_idx64 flag
//   1. init_deg    deg[i] = 1 (self loop)
//   2. count       deg[dst]++ per edge (atomic)
//   3. scan        rowptr = exscan(deg); self loop placed first; pos=rowptr+1
//   4. scatter     esrc[pos[dst]++] = src (atomic)
//   5. sgemm       h = x @ W  (fp32 128x128x16, double buffered)
//   6. attn dots   a_s[i,h] = <h[i,h,:], att_src[h]>, a_d likewise
//   7. aggregate   warp per dst node, one-pass online softmax over CSR edges
// ---------------------------------------------------------------------------

#define N_NODES_MAX 50000
#define N_EDGES_MAX 800000
#define E_TOT_MAX   (N_EDGES_MAX + N_NODES_MAX)
#define IN_DIM  256
#define OUT_DIM 64
#define HEADS   4
#define FDIM    (HEADS * OUT_DIM)   // 256
#define NEG_SLOPE 0.2f

// -------------------- scratch (static device arrays, 16B aligned) ----------
__device__ __align__(16) float g_h [(size_t)N_NODES_MAX * FDIM];
__device__ float g_as[(size_t)N_NODES_MAX * HEADS];
__device__ float g_ad[(size_t)N_NODES_MAX * HEADS];
__device__ int   g_deg[N_NODES_MAX];
__device__ int   g_rowptr[N_NODES_MAX + 1];
__device__ int   g_pos[N_NODES_MAX];
__device__ int   g_esrc[E_TOT_MAX];
__device__ int   g_idx64;   // 1 if edge_index is int64, 0 if int32

// decode edge-index element i from a raw 32-bit view, honoring dtype flag
__device__ __forceinline__ int edge_at(const int* __restrict__ w, int i,
                                       int is64, int n) {
    int v = is64 ? w[2 * i] : w[i];   // int64 values < 2^31: low word suffices
    // clamp: bad data degrades to wrong answer, never an address-space trap
    v = (v < 0) ? 0 : v;
    return (v >= n) ? (n - 1) : v;
}

// -------------------- 0. dtype sniff ----------------------------------------
// For int64 node ids (< 2^31), every odd 32-bit word is zero. For int32 random
// ids in [0, 50000), 2048 consecutive odd words being all zero is impossible.
__global__ void detect_kernel(const int* __restrict__ w, int e) {
    __shared__ int nz;
    if (threadIdx.x == 0) nz = 0;
    __syncthreads();
    int pairs = min(e, 2048);            // first 2048 (lo,hi) word pairs
    int bad = 0;
    for (int i = threadIdx.x; i < pairs; i += blockDim.x)
        if (w[2 * i + 1] != 0) bad++;
    if (bad) atomicAdd(&nz, bad);
    __syncthreads();
    if (threadIdx.x == 0) g_idx64 = (nz == 0) ? 1 : 0;
}

// -------------------- 1. init degrees ---------------------------------------
__global__ void init_deg_kernel(int n) {
    int i = blockIdx.x * blockDim.x + threadIdx.x;
    if (i < n) g_deg[i] = 1;
}

// -------------------- 2. count incoming edges --------------------------------
__global__ void count_kernel(const int* __restrict__ w, int e, int n) {
    int i = blockIdx.x * blockDim.x + threadIdx.x;
    if (i >= e) return;
    int is64 = g_idx64;
    int d = edge_at(w, e + i, is64, n);   // dst row = second E elements
    atomicAdd(&g_deg[d], 1);
}

// -------------------- 3. single-block exclusive scan -------------------------
__global__ void scan_kernel(int n) {
    const int T = 1024;
    int t = threadIdx.x;
    int lane = t & 31, wid = t >> 5;
    int per = (n + T - 1) / T;
    int start = t * per;
    if (start > n) start = n;
    int end = min(start + per, n);

    int s = 0;
    for (int i = start; i < end; i++) s += g_deg[i];

    int v = s;
    #pragma unroll
    for (int o = 1; o < 32; o <<= 1) {
        int u = __shfl_up_sync(0xffffffffu, v, o);
        if (lane >= o) v += u;
    }
    __shared__ int wtot[32];
    if (lane == 31) wtot[wid] = v;
    __syncthreads();
    if (wid == 0) {
        int w = wtot[lane];
        int vw = w;
        #pragma unroll
        for (int o = 1; o < 32; o <<= 1) {
            int u = __shfl_up_sync(0xffffffffu, vw, o);
            if (lane >= o) vw += u;
        }
        wtot[lane] = vw - w;          // exclusive warp offsets
    }
    __syncthreads();

    int acc = wtot[wid] + (v - s);    // exclusive prefix for this thread chunk
    for (int i = start; i < end; i++) {
        int d = g_deg[i];
        g_rowptr[i] = acc;
        g_esrc[acc] = i;              // self loop first (deterministic slot)
        g_pos[i]    = acc + 1;
        acc += d;
    }
    if (t == T - 1) g_rowptr[n] = acc;
}

// -------------------- 4. scatter edges into CSR ------------------------------
__global__ void scatter_kernel(const int* __restrict__ w, int e, int n) {
    int i = blockIdx.x * blockDim.x + threadIdx.x;
    if (i >= e) return;
    int is64 = g_idx64;
    int srow = edge_at(w, i,     is64, n);
    int d    = edge_at(w, e + i, is64, n);
    int p = atomicAdd(&g_pos[d], 1);
    g_esrc[p] = srow;
}

// -------------------- 5. SGEMM: h = x @ W  (M x 256 x 256) -------------------
#define BM 128
#define BN 128
#define BK 16
#define BMP 132   // padded row (528 B, multiple of 16 B)

#define GEMM_LOADG(k0)                                                         \
    do {                                                                       \
        int ga0 = bm + arow0, ga1 = bm + arow1;                                \
        pa0 = (ga0 < M) ? *(const float4*)(A + (size_t)ga0 * IN_DIM + (k0) + acol) : zero4; \
        pa1 = (ga1 < M) ? *(const float4*)(A + (size_t)ga1 * IN_DIM + (k0) + acol) : zero4; \
        pb0 = *(const float4*)(B + (size_t)((k0) + brow0) * FDIM + bn + bcol); \
        pb1 = *(const float4*)(B + (size_t)((k0) + brow1) * FDIM + bn + bcol); \
    } while (0)

#define GEMM_STORES(st)                                                        \
    do {                                                                       \
        As[st][acol + 0][arow0] = pa0.x;                                       \
        As[st][acol + 1][arow0] = pa0.y;                                       \
        As[st][acol + 2][arow0] = pa0.z;                                       \
        As[st][acol + 3][arow0] = pa0.w;                                       \
        As[st][acol + 0][arow1] = pa1.x;                                       \
        As[st][acol + 1][arow1] = pa1.y;                                       \
        As[st][acol + 2][arow1] = pa1.z;                                       \
        As[st][acol + 3][arow1] = pa1.w;                                       \
        *(float4*)&Bs[st][brow0][bcol] = pb0;                                  \
        *(float4*)&Bs[st][brow1][bcol] = pb1;                                  \
    } while (0)

__global__ void __launch_bounds__(256)
gemm_kernel(const float* __restrict__ A, const float* __restrict__ B, int M) {
    __shared__ __align__(16) float As[2][BK][BMP];
    __shared__ __align__(16) float Bs[2][BK][BN];

    const int tid = threadIdx.x;
    const int bm  = blockIdx.x * BM;
    const int bn  = blockIdx.y * BN;
    const int tx  = tid & 15;
    const int ty  = tid >> 4;

    const int arow0 = tid >> 2;          // 0..63
    const int arow1 = arow0 + 64;        // 64..127
    const int acol  = (tid & 3) << 2;    // 0,4,8,12
    const int brow0 = tid >> 5;          // 0..7
    const int brow1 = brow0 + 8;         // 8..15
    const int bcol  = (tid & 31) << 2;   // 0..124 step 4

    const float4 zero4 = make_float4(0.f, 0.f, 0.f, 0.f);
    float4 pa0, pa1, pb0, pb1;

    float acc[8][8];
    #pragma unroll
    for (int i = 0; i < 8; i++)
        #pragma unroll
        for (int j = 0; j < 8; j++) acc[i][j] = 0.f;

    GEMM_LOADG(0);
    GEMM_STORES(0);
    __syncthreads();

    int s = 0;
    for (int k0 = 0; k0 < IN_DIM; k0 += BK) {
        const bool more = (k0 + BK) < IN_DIM;
        if (more) GEMM_LOADG(k0 + BK);

        #pragma unroll
        for (int kk = 0; kk < BK; kk++) {
            float4 a0 = *(const float4*)&As[s][kk][ty * 4];
            float4 a1 = *(const float4*)&As[s][kk][ty * 4 + 64];
            float4 b0 = *(const float4*)&Bs[s][kk][tx * 4];
            float4 b1 = *(const float4*)&Bs[s][kk][tx * 4 + 64];
            float av[8] = {a0.x, a0.y, a0.z, a0.w, a1.x, a1.y, a1.z, a1.w};
            float bv[8] = {b0.x, b0.y, b0.z, b0.w, b1.x, b1.y, b1.z, b1.w};
            #pragma unroll
            for (int i = 0; i < 8; i++)
                #pragma unroll
                for (int j = 0; j < 8; j++)
                    acc[i][j] = fmaf(av[i], bv[j], acc[i][j]);
        }
        if (more) GEMM_STORES(s ^ 1);
        __syncthreads();
        s ^= 1;
    }

    #pragma unroll
    for (int i = 0; i < 8; i++) {
        int gm = bm + ty * 4 + ((i < 4) ? i : 60 + i);  // i>=4 -> +64+(i-4)
        if (gm < M) {
            float* orow = g_h + (size_t)gm * FDIM + bn + tx * 4;
            *(float4*)(orow)      = make_float4(acc[i][0], acc[i][1], acc[i][2], acc[i][3]);
            *(float4*)(orow + 64) = make_float4(acc[i][4], acc[i][5], acc[i][6], acc[i][7]);
        }
    }
}

// -------------------- 6. attention dots: warp per node -----------------------
__global__ void attn_kernel(const float* __restrict__ att_src,
                            const float* __restrict__ att_dst, int n) {
    int warp = (blockIdx.x * blockDim.x + threadIdx.x) >> 5;
    int lane = threadIdx.x & 31;
    if (warp >= n) return;

    int head = lane >> 3;                 // 8 lanes per head
    int off  = (lane & 7) * 8;            // slot inside head's 64 floats
    const float* hrow = g_h + (size_t)warp * FDIM + lane * 8;
    const float* asv  = att_src + head * OUT_DIM + off;
    const float* adv  = att_dst + head * OUT_DIM + off;

    float4 v0 = *(const float4*)(hrow);
    float4 v1 = *(const float4*)(hrow + 4);
    float4 a0 = *(const float4*)(asv);
    float4 a1 = *(const float4*)(asv + 4);
    float4 d0 = *(const float4*)(adv);
    float4 d1 = *(const float4*)(adv + 4);

    float ss = v0.x*a0.x + v0.y*a0.y + v0.z*a0.z + v0.w*a0.w
             + v1.x*a1.x + v1.y*a1.y + v1.z*a1.z + v1.w*a1.w;
    float dd = v0.x*d0.x + v0.y*d0.y + v0.z*d0.z + v0.w*d0.w
             + v1.x*d1.x + v1.y*d1.y + v1.z*d1.z + v1.w*d1.w;

    #pragma unroll
    for (int o = 4; o > 0; o >>= 1) {
        ss += __shfl_down_sync(0xffffffffu, ss, o);
        dd += __shfl_down_sync(0xffffffffu, dd, o);
    }
    if ((lane & 7) == 0) {
        g_as[warp * HEADS + head] = ss;
        g_ad[warp * HEADS + head] = dd;
    }
}

// -------------------- 7. aggregation: warp per dst node ----------------------
// lane l owns features [l*4, l*4+4) (head h1 = l>>4) and
//                      [128+l*4, ...) (head h2 = 2 + (l>>4)).
// Online softmax (m,d rescale) — one pass, no atomics.
__global__ void aggregate_kernel(const float* __restrict__ bias,
                                 float* __restrict__ out, int n) {
    int node = (blockIdx.x * blockDim.x + threadIdx.x) >> 5;
    int lane = threadIdx.x & 31;
    if (node >= n) return;

    int beg = g_rowptr[node];
    int end = g_rowptr[node + 1];

    const int h1 = lane >> 4;
    const int h2 = 2 + (lane >> 4);
    const float ad1 = g_ad[node * HEADS + h1];
    const float ad2 = g_ad[node * HEADS + h2];

    float m1 = -CUDART_INF_F, m2 = -CUDART_INF_F;
    float d1 = 0.f, d2 = 0.f;
    float4 acc1 = make_float4(0.f, 0.f, 0.f, 0.f);
    float4 acc2 = make_float4(0.f, 0.f, 0.f, 0.f);

    for (int p = beg; p < end; p++) {
        int s = g_esrc[p];
        float as1 = g_as[s * HEADS + h1];
        float as2 = g_as[s * HEADS + h2];
        float e1 = as1 + ad1; e1 = (e1 > 0.f) ? e1 : NEG_SLOPE * e1;
        float e2 = as2 + ad2; e2 = (e2 > 0.f) ? e2 : NEG_SLOPE * e2;

        float nm1 = fmaxf(m1, e1);
        float nm2 = fmaxf(m2, e2);
        float sc1 = __expf(m1 - nm1);   // 0 on first edge, 1 if max unchanged
        float sc2 = __expf(m2 - nm2);
        float w1  = __expf(e1 - nm1);
        float w2  = __expf(e2 - nm2);
        m1 = nm1; m2 = nm2;
        d1 = d1 * sc1 + w1;
        d2 = d2 * sc2 + w2;

        const float* hb = g_h + (size_t)s * FDIM + lane * 4;
        float4 hv1 = *(const float4*)(hb);
        float4 hv2 = *(const float4*)(hb + 128);

        acc1.x = acc1.x * sc1 + w1 * hv1.x;
        acc1.y = acc1.y * sc1 + w1 * hv1.y;
        acc1.z = acc1.z * sc1 + w1 * hv1.z;
        acc1.w = acc1.w * sc1 + w1 * hv1.w;
        acc2.x = acc2.x * sc2 + w2 * hv2.x;
        acc2.y = acc2.y * sc2 + w2 * hv2.y;
        acc2.z = acc2.z * sc2 + w2 * hv2.z;
        acc2.w = acc2.w * sc2 + w2 * hv2.w;
    }

    float inv1 = 1.f / (d1 + 1e-16f);
    float inv2 = 1.f / (d2 + 1e-16f);
    int f1 = lane * 4;
    int f2 = 128 + lane * 4;
    float4 b1 = *(const float4*)(bias + f1);
    float4 b2 = *(const float4*)(bias + f2);

    float4 o1, o2;
    o1.x = fmaxf(acc1.x * inv1 + b1.x, 0.f);
    o1.y = fmaxf(acc1.y * inv1 + b1.y, 0.f);
    o1.z = fmaxf(acc1.z * inv1 + b1.z, 0.f);
    o1.w = fmaxf(acc1.w * inv1 + b1.w, 0.f);
    o2.x = fmaxf(acc2.x * inv2 + b2.x, 0.f);
    o2.y = fmaxf(acc2.y * inv2 + b2.y, 0.f);
    o2.z = fmaxf(acc2.z * inv2 + b2.z, 0.f);
    o2.w = fmaxf(acc2.w * inv2 + b2.w, 0.f);

    float* orow = out + (size_t)node * FDIM;
    *(float4*)(orow + f1) = o1;
    *(float4*)(orow + f2) = o2;
}

// ---------------------------------------------------------------------------
extern "C" void kernel_launch(void* const* d_in, const int* in_sizes, int n_in,
                              void* d_out, int out_size) {
    const float* x       = (const float*)d_in[0];
    const int*   ew      = (const int*)d_in[1];   // raw 32-bit view of edge_index
    const float* W       = (const float*)d_in[2];
    const float* att_src = (const float*)d_in[3];
    const float* att_dst = (const float*)d_in[4];
    const float* bias    = (const float*)d_in[5];
    float*       out     = (float*)d_out;

    int N = in_sizes[0] / IN_DIM;   // 50000
    int E = in_sizes[1] / 2;        // 800000 (element count same for i32/i64)

    // 0. dtype sniff + CSR build
    detect_kernel<<<1, 256>>>(ew, E);
    init_deg_kernel<<<(N + 255) / 256, 256>>>(N);
    count_kernel<<<(E + 255) / 256, 256>>>(ew, E, N);
    scan_kernel<<<1, 1024>>>(N);
    scatter_kernel<<<(E + 255) / 256, 256>>>(ew, E, N);

    // projection + attention dots
    dim3 ggrid((N + BM - 1) / BM, FDIM / BN);
    gemm_kernel<<<ggrid, 256>>>(x, W, N);
    attn_kernel<<<((N * 32) + 255) / 256, 256>>>(att_src, att_dst, N);

    // softmax-aggregate
    aggregate_kernel<<<((N * 32) + 255) / 256, 256>>>(bias, out, N);
}

// round 7
// speedup vs baseline: 1.3487x; 1.3487x over previous
#include <cuda_runtime.h>
#include <cuda_bf16.h>
#include <math_constants.h>

// ---------------------------------------------------------------------------
// GAT layer: out = relu( segment_softmax_aggregate( leaky_relu(a_s[j]+a_d[i]),
//                                                   h[j] ) + bias )
// h = x @ W, self loops added, softmax over incoming edges per dst node.
//
// Pipeline (stream-ordered, graph-capturable, allocation-free):
//   0. detect      edge_index dtype sniff (int32 vs int64) -> g_idx64 flag
//   1. init_deg    deg[i] = 1 (self loop)
//   2. count       deg[dst]++ per edge (atomic)
//   3. partial     per-block sums of deg               (196 blocks)
//   4. bsum_scan   exclusive scan of block sums (1 blk), writes rowptr[N]
//   5. emit        per-block exclusive scan + offset -> rowptr/esrc/pos
//   6. scatter     esrc[pos[dst]++] = src (atomic)
//   7. sgemm       h = x @ W  (fp32 128x128x16, double buffered)
//   8. attn dots   a_s[i,h] = <h[i,h,:], att_src[h]>, a_d likewise
//   9. aggregate   warp per dst node, one-pass online softmax over CSR edges
// ---------------------------------------------------------------------------

#define N_NODES_MAX 50000
#define N_EDGES_MAX 800000
#define E_TOT_MAX   (N_EDGES_MAX + N_NODES_MAX)
#define IN_DIM  256
#define OUT_DIM 64
#define HEADS   4
#define FDIM    (HEADS * OUT_DIM)   // 256
#define NEG_SLOPE 0.2f

#define SCAN_BLK 256
#define SCAN_NBLK ((N_NODES_MAX + SCAN_BLK - 1) / SCAN_BLK)   // 196

// -------------------- scratch (static device arrays, 16B aligned) ----------
__device__ __align__(16) float g_h [(size_t)N_NODES_MAX * FDIM];
__device__ float g_as[(size_t)N_NODES_MAX * HEADS];
__device__ float g_ad[(size_t)N_NODES_MAX * HEADS];
__device__ int   g_deg[N_NODES_MAX];
__device__ int   g_rowptr[N_NODES_MAX + 1];
__device__ int   g_pos[N_NODES_MAX];
__device__ int   g_esrc[E_TOT_MAX];
__device__ int   g_bsum[1024];
__device__ int   g_boff[1024];
__device__ int   g_idx64;   // 1 if edge_index is int64, 0 if int32

// decode edge-index element i from a raw 32-bit view, honoring dtype flag
__device__ __forceinline__ int edge_at(const int* __restrict__ w, int i,
                                       int is64, int n) {
    int v = is64 ? w[2 * i] : w[i];   // int64 ids < 2^31: low word suffices
    v = (v < 0) ? 0 : v;
    return (v >= n) ? (n - 1) : v;    // clamp: degrade, never trap
}

// -------------------- 0. dtype sniff ----------------------------------------
__global__ void detect_kernel(const int* __restrict__ w, int e) {
    __shared__ int nz;
    if (threadIdx.x == 0) nz = 0;
    __syncthreads();
    int pairs = min(e, 2048);
    int bad = 0;
    for (int i = threadIdx.x; i < pairs; i += blockDim.x)
        if (w[2 * i + 1] != 0) bad++;
    if (bad) atomicAdd(&nz, bad);
    __syncthreads();
    if (threadIdx.x == 0) g_idx64 = (nz == 0) ? 1 : 0;
}

// -------------------- 1. init degrees ---------------------------------------
__global__ void init_deg_kernel(int n) {
    int i = blockIdx.x * blockDim.x + threadIdx.x;
    if (i < n) g_deg[i] = 1;
}

// -------------------- 2. count incoming edges --------------------------------
__global__ void count_kernel(const int* __restrict__ w, int e, int n) {
    int i = blockIdx.x * blockDim.x + threadIdx.x;
    if (i >= e) return;
    int is64 = g_idx64;
    int d = edge_at(w, e + i, is64, n);
    atomicAdd(&g_deg[d], 1);
}

// -------------------- 3. per-block degree sums -------------------------------
__global__ void partial_kernel(int n) {
    int i = blockIdx.x * blockDim.x + threadIdx.x;
    int lane = threadIdx.x & 31, wid = threadIdx.x >> 5;
    int d = (i < n) ? g_deg[i] : 0;

    int v = d;
    #pragma unroll
    for (int o = 16; o > 0; o >>= 1) v += __shfl_down_sync(0xffffffffu, v, o);
    __shared__ int ws[8];
    if (lane == 0) ws[wid] = v;
    __syncthreads();
    if (wid == 0) {
        int t = (lane < (SCAN_BLK >> 5)) ? ws[lane] : 0;
        #pragma unroll
        for (int o = 4; o > 0; o >>= 1) t += __shfl_down_sync(0xffffffffu, t, o);
        if (lane == 0) g_bsum[blockIdx.x] = t;
    }
}

// -------------------- 4. scan of block sums (single small block) -------------
__global__ void bsum_scan_kernel(int nblk, int n) {
    int t = threadIdx.x;             // blockDim.x = 256 >= nblk (196)
    int lane = t & 31, wid = t >> 5;
    int v = (t < nblk) ? g_bsum[t] : 0;
    int s = v;

    #pragma unroll
    for (int o = 1; o < 32; o <<= 1) {
        int u = __shfl_up_sync(0xffffffffu, v, o);
        if (lane >= o) v += u;
    }
    __shared__ int ws[8];
    if (lane == 31) ws[wid] = v;
    __syncthreads();
    if (wid == 0 && lane < 8) {
        int w = ws[lane];
        int vw = w;
        #pragma unroll
        for (int o = 1; o < 8; o <<= 1) {
            int u = __shfl_up_sync(0xffu, vw, o);
            if (lane >= o) vw += u;
        }
        ws[lane] = vw - w;           // exclusive warp offsets
    }
    __syncthreads();

    int excl = ws[wid] + (v - s);
    if (t < nblk) g_boff[t] = excl;
    if (t == nblk - 1) g_rowptr[n] = excl + s;   // total edges incl. self loops
}

// -------------------- 5. emit rowptr / self-loop / pos -----------------------
__global__ void emit_kernel(int n) {
    int i = blockIdx.x * blockDim.x + threadIdx.x;
    int lane = threadIdx.x & 31, wid = threadIdx.x >> 5;
    int d = (i < n) ? g_deg[i] : 0;

    int v = d;
    #pragma unroll
    for (int o = 1; o < 32; o <<= 1) {
        int u = __shfl_up_sync(0xffffffffu, v, o);
        if (lane >= o) v += u;
    }
    __shared__ int ws[8];
    if (lane == 31) ws[wid] = v;
    __syncthreads();
    if (wid == 0 && lane < 8) {
        int w = ws[lane];
        int vw = w;
        #pragma unroll
        for (int o = 1; o < 8; o <<= 1) {
            int u = __shfl_up_sync(0xffu, vw, o);
            if (lane >= o) vw += u;
        }
        ws[lane] = vw - w;
    }
    __syncthreads();

    if (i < n) {
        int acc = g_boff[blockIdx.x] + ws[wid] + (v - d);  // global excl prefix
        g_rowptr[i] = acc;
        g_esrc[acc] = i;             // self loop first (deterministic slot)
        g_pos[i]    = acc + 1;
    }
}

// -------------------- 6. scatter edges into CSR ------------------------------
__global__ void scatter_kernel(const int* __restrict__ w, int e, int n) {
    int i = blockIdx.x * blockDim.x + threadIdx.x;
    if (i >= e) return;
    int is64 = g_idx64;
    int srow = edge_at(w, i,     is64, n);
    int d    = edge_at(w, e + i, is64, n);
    int p = atomicAdd(&g_pos[d], 1);
    g_esrc[p] = srow;
}

// -------------------- 7. SGEMM: h = x @ W  (M x 256 x 256) -------------------
#define BM 128
#define BN 128
#define BK 16
#define BMP 132

#define GEMM_LOADG(k0)                                                         \
    do {                                                                       \
        int ga0 = bm + arow0, ga1 = bm + arow1;                                \
        pa0 = (ga0 < M) ? *(const float4*)(A + (size_t)ga0 * IN_DIM + (k0) + acol) : zero4; \
        pa1 = (ga1 < M) ? *(const float4*)(A + (size_t)ga1 * IN_DIM + (k0) + acol) : zero4; \
        pb0 = *(const float4*)(B + (size_t)((k0) + brow0) * FDIM + bn + bcol); \
        pb1 = *(const float4*)(B + (size_t)((k0) + brow1) * FDIM + bn + bcol); \
    } while (0)

#define GEMM_STORES(st)                                                        \
    do {                                                                       \
        As[st][acol + 0][arow0] = pa0.x;                                       \
        As[st][acol + 1][arow0] = pa0.y;                                       \
        As[st][acol + 2][arow0] = pa0.z;                                       \
        As[st][acol + 3][arow0] = pa0.w;                                       \
        As[st][acol + 0][arow1] = pa1.x;                                       \
        As[st][acol + 1][arow1] = pa1.y;                                       \
        As[st][acol + 2][arow1] = pa1.z;                                       \
        As[st][acol + 3][arow1] = pa1.w;                                       \
        *(float4*)&Bs[st][brow0][bcol] = pb0;                                  \
        *(float4*)&Bs[st][brow1][bcol] = pb1;                                  \
    } while (0)

__global__ void __launch_bounds__(256)
gemm_kernel(const float* __restrict__ A, const float* __restrict__ B, int M) {
    __shared__ __align__(16) float As[2][BK][BMP];
    __shared__ __align__(16) float Bs[2][BK][BN];

    const int tid = threadIdx.x;
    const int bm  = blockIdx.x * BM;
    const int bn  = blockIdx.y * BN;
    const int tx  = tid & 15;
    const int ty  = tid >> 4;

    const int arow0 = tid >> 2;
    const int arow1 = arow0 + 64;
    const int acol  = (tid & 3) << 2;
    const int brow0 = tid >> 5;
    const int brow1 = brow0 + 8;
    const int bcol  = (tid & 31) << 2;

    const float4 zero4 = make_float4(0.f, 0.f, 0.f, 0.f);
    float4 pa0, pa1, pb0, pb1;

    float acc[8][8];
    #pragma unroll
    for (int i = 0; i < 8; i++)
        #pragma unroll
        for (int j = 0; j < 8; j++) acc[i][j] = 0.f;

    GEMM_LOADG(0);
    GEMM_STORES(0);
    __syncthreads();

    int s = 0;
    for (int k0 = 0; k0 < IN_DIM; k0 += BK) {
        const bool more = (k0 + BK) < IN_DIM;
        if (more) GEMM_LOADG(k0 + BK);

        #pragma unroll
        for (int kk = 0; kk < BK; kk++) {
            float4 a0 = *(const float4*)&As[s][kk][ty * 4];
            float4 a1 = *(const float4*)&As[s][kk][ty * 4 + 64];
            float4 b0 = *(const float4*)&Bs[s][kk][tx * 4];
            float4 b1 = *(const float4*)&Bs[s][kk][tx * 4 + 64];
            float av[8] = {a0.x, a0.y, a0.z, a0.w, a1.x, a1.y, a1.z, a1.w};
            float bv[8] = {b0.x, b0.y, b0.z, b0.w, b1.x, b1.y, b1.z, b1.w};
            #pragma unroll
            for (int i = 0; i < 8; i++)
                #pragma unroll
                for (int j = 0; j < 8; j++)
                    acc[i][j] = fmaf(av[i], bv[j], acc[i][j]);
        }
        if (more) GEMM_STORES(s ^ 1);
        __syncthreads();
        s ^= 1;
    }

    #pragma unroll
    for (int i = 0; i < 8; i++) {
        int gm = bm + ty * 4 + ((i < 4) ? i : 60 + i);
        if (gm < M) {
            float* orow = g_h + (size_t)gm * FDIM + bn + tx * 4;
            *(float4*)(orow)      = make_float4(acc[i][0], acc[i][1], acc[i][2], acc[i][3]);
            *(float4*)(orow + 64) = make_float4(acc[i][4], acc[i][5], acc[i][6], acc[i][7]);
        }
    }
}

// -------------------- 8. attention dots: warp per node -----------------------
__global__ void attn_kernel(const float* __restrict__ att_src,
                            const float* __restrict__ att_dst, int n) {
    int warp = (blockIdx.x * blockDim.x + threadIdx.x) >> 5;
    int lane = threadIdx.x & 31;
    if (warp >= n) return;

    int head = lane >> 3;
    int off  = (lane & 7) * 8;
    const float* hrow = g_h + (size_t)warp * FDIM + lane * 8;
    const float* asv  = att_src + head * OUT_DIM + off;
    const float* adv  = att_dst + head * OUT_DIM + off;

    float4 v0 = *(const float4*)(hrow);
    float4 v1 = *(const float4*)(hrow + 4);
    float4 a0 = *(const float4*)(asv);
    float4 a1 = *(const float4*)(asv + 4);
    float4 d0 = *(const float4*)(adv);
    float4 d1 = *(const float4*)(adv + 4);

    float ss = v0.x*a0.x + v0.y*a0.y + v0.z*a0.z + v0.w*a0.w
             + v1.x*a1.x + v1.y*a1.y + v1.z*a1.z + v1.w*a1.w;
    float dd = v0.x*d0.x + v0.y*d0.y + v0.z*d0.z + v0.w*d0.w
             + v1.x*d1.x + v1.y*d1.y + v1.z*d1.z + v1.w*d1.w;

    #pragma unroll
    for (int o = 4; o > 0; o >>= 1) {
        ss += __shfl_down_sync(0xffffffffu, ss, o);
        dd += __shfl_down_sync(0xffffffffu, dd, o);
    }
    if ((lane & 7) == 0) {
        g_as[warp * HEADS + head] = ss;
        g_ad[warp * HEADS + head] = dd;
    }
}

// -------------------- 9. aggregation: warp per dst node ----------------------
__global__ void aggregate_kernel(const float* __restrict__ bias,
                                 float* __restrict__ out, int n) {
    int node = (blockIdx.x * blockDim.x + threadIdx.x) >> 5;
    int lane = threadIdx.x & 31;
    if (node >= n) return;

    int beg = g_rowptr[node];
    int end = g_rowptr[node + 1];

    const int h1 = lane >> 4;
    const int h2 = 2 + (lane >> 4);
    const float ad1 = g_ad[node * HEADS + h1];
    const float ad2 = g_ad[node * HEADS + h2];

    float m1 = -CUDART_INF_F, m2 = -CUDART_INF_F;
    float d1 = 0.f, d2 = 0.f;
    float4 acc1 = make_float4(0.f, 0.f, 0.f, 0.f);
    float4 acc2 = make_float4(0.f, 0.f, 0.f, 0.f);

    for (int p = beg; p < end; p++) {
        int s = g_esrc[p];
        float as1 = g_as[s * HEADS + h1];
        float as2 = g_as[s * HEADS + h2];
        float e1 = as1 + ad1; e1 = (e1 > 0.f) ? e1 : NEG_SLOPE * e1;
        float e2 = as2 + ad2; e2 = (e2 > 0.f) ? e2 : NEG_SLOPE * e2;

        float nm1 = fmaxf(m1, e1);
        float nm2 = fmaxf(m2, e2);
        float sc1 = __expf(m1 - nm1);
        float sc2 = __expf(m2 - nm2);
        float w1  = __expf(e1 - nm1);
        float w2  = __expf(e2 - nm2);
        m1 = nm1; m2 = nm2;
        d1 = d1 * sc1 + w1;
        d2 = d2 * sc2 + w2;

        const float* hb = g_h + (size_t)s * FDIM + lane * 4;
        float4 hv1 = *(const float4*)(hb);
        float4 hv2 = *(const float4*)(hb + 128);

        acc1.x = acc1.x * sc1 + w1 * hv1.x;
        acc1.y = acc1.y * sc1 + w1 * hv1.y;
        acc1.z = acc1.z * sc1 + w1 * hv1.z;
        acc1.w = acc1.w * sc1 + w1 * hv1.w;
        acc2.x = acc2.x * sc2 + w2 * hv2.x;
        acc2.y = acc2.y * sc2 + w2 * hv2.y;
        acc2.z = acc2.z * sc2 + w2 * hv2.z;
        acc2.w = acc2.w * sc2 + w2 * hv2.w;
    }

    float inv1 = 1.f / (d1 + 1e-16f);
    float inv2 = 1.f / (d2 + 1e-16f);
    int f1 = lane * 4;
    int f2 = 128 + lane * 4;
    float4 b1 = *(const float4*)(bias + f1);
    float4 b2 = *(const float4*)(bias + f2);

    float4 o1, o2;
    o1.x = fmaxf(acc1.x * inv1 + b1.x, 0.f);
    o1.y = fmaxf(acc1.y * inv1 + b1.y, 0.f);
    o1.z = fmaxf(acc1.z * inv1 + b1.z, 0.f);
    o1.w = fmaxf(acc1.w * inv1 + b1.w, 0.f);
    o2.x = fmaxf(acc2.x * inv2 + b2.x, 0.f);
    o2.y = fmaxf(acc2.y * inv2 + b2.y, 0.f);
    o2.z = fmaxf(acc2.z * inv2 + b2.z, 0.f);
    o2.w = fmaxf(acc2.w * inv2 + b2.w, 0.f);

    float* orow = out + (size_t)node * FDIM;
    *(float4*)(orow + f1) = o1;
    *(float4*)(orow + f2) = o2;
}

// ---------------------------------------------------------------------------
extern "C" void kernel_launch(void* const* d_in, const int* in_sizes, int n_in,
                              void* d_out, int out_size) {
    const float* x       = (const float*)d_in[0];
    const int*   ew      = (const int*)d_in[1];   // raw 32-bit view of edge_index
    const float* W       = (const float*)d_in[2];
    const float* att_src = (const float*)d_in[3];
    const float* att_dst = (const float*)d_in[4];
    const float* bias    = (const float*)d_in[5];
    float*       out     = (float*)d_out;

    int N = in_sizes[0] / IN_DIM;   // 50000
    int E = in_sizes[1] / 2;        // 800000
    int nblk = (N + SCAN_BLK - 1) / SCAN_BLK;

    // CSR build (parallel decoupled scan)
    detect_kernel<<<1, 256>>>(ew, E);
    init_deg_kernel<<<(N + 255) / 256, 256>>>(N);
    count_kernel<<<(E + 255) / 256, 256>>>(ew, E, N);
    partial_kernel<<<nblk, SCAN_BLK>>>(N);
    bsum_scan_kernel<<<1, 256>>>(nblk, N);
    emit_kernel<<<nblk, SCAN_BLK>>>(N);
    scatter_kernel<<<(E + 255) / 256, 256>>>(ew, E, N);

    // projection + attention dots
    dim3 ggrid((N + BM - 1) / BM, FDIM / BN);
    gemm_kernel<<<ggrid, 256>>>(x, W, N);
    attn_kernel<<<((N * 32) + 255) / 256, 256>>>(att_src, att_dst, N);

    // softmax-aggregate
    aggregate_kernel<<<((N * 32) + 255) / 256, 256>>>(bias, out, N);
}

// round 10
// speedup vs baseline: 1.4377x; 1.0660x over previous
#include <cuda_runtime.h>
#include <cuda_bf16.h>
#include <math_constants.h>
#include <cstdint>

// ---------------------------------------------------------------------------
// GAT layer: out = relu( segment_softmax_aggregate( leaky_relu(a_s[j]+a_d[i]),
//                                                   h[j] ) + bias )
// h = x @ W, self loops added, softmax over incoming edges per dst node.
//
// Pipeline (stream-ordered, graph-capturable, allocation-free):
//   0. detect      edge_index dtype sniff (int32 vs int64) -> g_idx64 flag
//   1. init_deg    deg[i] = 1 (self loop)
//   2. count       deg[dst]++ per edge (atomic)
//   3. partial/bsum_scan/emit   decoupled exclusive scan -> rowptr/self/pos
//   4. scatter     esrc[pos[dst]++] = src (atomic)
//   5. sgemm       h = x @ W  (fp32, 128x128x16, packed fma.rn.f32x2)
//   6. attn dots   a_s[i,h] = <h[i,h,:], att_src[h]>, a_d likewise
//   7. aggregate   warp per dst node, one-pass online softmax over CSR edges
// ---------------------------------------------------------------------------

#define N_NODES_MAX 50000
#define N_EDGES_MAX 800000
#define E_TOT_MAX   (N_EDGES_MAX + N_NODES_MAX)
#define IN_DIM  256
#define OUT_DIM 64
#define HEADS   4
#define FDIM    (HEADS * OUT_DIM)   // 256
#define NEG_SLOPE 0.2f
#define SCAN_BLK 256

// -------------------- scratch (static device arrays, 16B aligned) ----------
__device__ __align__(16) float g_h [(size_t)N_NODES_MAX * FDIM];
__device__ float g_as[(size_t)N_NODES_MAX * HEADS];
__device__ float g_ad[(size_t)N_NODES_MAX * HEADS];
__device__ int   g_deg[N_NODES_MAX];
__device__ int   g_rowptr[N_NODES_MAX + 1];
__device__ int   g_pos[N_NODES_MAX];
__device__ int   g_esrc[E_TOT_MAX];
__device__ int   g_bsum[1024];
__device__ int   g_boff[1024];
__device__ int   g_idx64;

// decode edge-index element i from a raw 32-bit view, honoring dtype flag
__device__ __forceinline__ int edge_at(const int* __restrict__ w, int i,
                                       int is64, int n) {
    int v = is64 ? w[2 * i] : w[i];   // int64 ids < 2^31: low word suffices
    v = (v < 0) ? 0 : v;
    return (v >= n) ? (n - 1) : v;    // clamp: degrade, never trap
}

// -------------------- 0. dtype sniff ----------------------------------------
__global__ void detect_kernel(const int* __restrict__ w, int e) {
    __shared__ int nz;
    if (threadIdx.x == 0) nz = 0;
    __syncthreads();
    int pairs = min(e, 2048);
    int bad = 0;
    for (int i = threadIdx.x; i < pairs; i += blockDim.x)
        if (w[2 * i + 1] != 0) bad++;
    if (bad) atomicAdd(&nz, bad);
    __syncthreads();
    if (threadIdx.x == 0) g_idx64 = (nz == 0) ? 1 : 0;
}

// -------------------- 1. init degrees ---------------------------------------
__global__ void init_deg_kernel(int n) {
    int i = blockIdx.x * blockDim.x + threadIdx.x;
    if (i < n) g_deg[i] = 1;
}

// -------------------- 2. count incoming edges --------------------------------
__global__ void count_kernel(const int* __restrict__ w, int e, int n) {
    int i = blockIdx.x * blockDim.x + threadIdx.x;
    if (i >= e) return;
    atomicAdd(&g_deg[edge_at(w, e + i, g_idx64, n)], 1);
}

// -------------------- 3a. per-block degree sums ------------------------------
__global__ void partial_kernel(int n) {
    int i = blockIdx.x * blockDim.x + threadIdx.x;
    int lane = threadIdx.x & 31, wid = threadIdx.x >> 5;
    int v = (i < n) ? g_deg[i] : 0;
    #pragma unroll
    for (int o = 16; o > 0; o >>= 1) v += __shfl_down_sync(0xffffffffu, v, o);
    __shared__ int ws[8];
    if (lane == 0) ws[wid] = v;
    __syncthreads();
    if (wid == 0) {
        int t = (lane < 8) ? ws[lane] : 0;
        #pragma unroll
        for (int o = 4; o > 0; o >>= 1) t += __shfl_down_sync(0xffffffffu, t, o);
        if (lane == 0) g_bsum[blockIdx.x] = t;
    }
}

// -------------------- 3b. scan of block sums ---------------------------------
__global__ void bsum_scan_kernel(int nblk, int n) {
    int t = threadIdx.x, lane = t & 31, wid = t >> 5;
    int v = (t < nblk) ? g_bsum[t] : 0;
    int s = v;
    #pragma unroll
    for (int o = 1; o < 32; o <<= 1) {
        int u = __shfl_up_sync(0xffffffffu, v, o);
        if (lane >= o) v += u;
    }
    __shared__ int ws[8];
    if (lane == 31) ws[wid] = v;
    __syncthreads();
    if (wid == 0 && lane < 8) {
        int w = ws[lane], vw = w;
        #pragma unroll
        for (int o = 1; o < 8; o <<= 1) {
            int u = __shfl_up_sync(0xffu, vw, o);
            if (lane >= o) vw += u;
        }
        ws[lane] = vw - w;
    }
    __syncthreads();
    int excl = ws[wid] + (v - s);
    if (t < nblk) g_boff[t] = excl;
    if (t == nblk - 1) g_rowptr[n] = excl + s;
}

// -------------------- 3c. emit rowptr / self-loop / pos ----------------------
__global__ void emit_kernel(int n) {
    int i = blockIdx.x * blockDim.x + threadIdx.x;
    int lane = threadIdx.x & 31, wid = threadIdx.x >> 5;
    int d = (i < n) ? g_deg[i] : 0;
    int v = d;
    #pragma unroll
    for (int o = 1; o < 32; o <<= 1) {
        int u = __shfl_up_sync(0xffffffffu, v, o);
        if (lane >= o) v += u;
    }
    __shared__ int ws[8];
    if (lane == 31) ws[wid] = v;
    __syncthreads();
    if (wid == 0 && lane < 8) {
        int w = ws[lane], vw = w;
        #pragma unroll
        for (int o = 1; o < 8; o <<= 1) {
            int u = __shfl_up_sync(0xffu, vw, o);
            if (lane >= o) vw += u;
        }
        ws[lane] = vw - w;
    }
    __syncthreads();
    if (i < n) {
        int acc = g_boff[blockIdx.x] + ws[wid] + (v - d);
        g_rowptr[i] = acc;
        g_esrc[acc] = i;             // self loop first (deterministic slot)
        g_pos[i]    = acc + 1;
    }
}

// -------------------- 4. scatter edges into CSR ------------------------------
__global__ void scatter_kernel(const int* __restrict__ w, int e, int n) {
    int i = blockIdx.x * blockDim.x + threadIdx.x;
    if (i >= e) return;
    int is64 = g_idx64;
    int srow = edge_at(w, i,     is64, n);
    int d    = edge_at(w, e + i, is64, n);
    int p = atomicAdd(&g_pos[d], 1);
    g_esrc[p] = srow;
}

// -------------------- 5. SGEMM: h = x @ W, packed f32x2 FMA ------------------
#define BM 128
#define BN 128
#define BK 16
#define BMP 132   // padded row (528 B, multiple of 16 B)

#define GEMM_LOADG(k0)                                                         \
    do {                                                                       \
        int ga0 = bm + arow0, ga1 = bm + arow1;                                \
        pa0 = (ga0 < M) ? *(const float4*)(A + (size_t)ga0 * IN_DIM + (k0) + acol) : zero4; \
        pa1 = (ga1 < M) ? *(const float4*)(A + (size_t)ga1 * IN_DIM + (k0) + acol) : zero4; \
        pb0 = *(const float4*)(B + (size_t)((k0) + brow0) * FDIM + bn + bcol); \
        pb1 = *(const float4*)(B + (size_t)((k0) + brow1) * FDIM + bn + bcol); \
    } while (0)

#define GEMM_STORES(st)                                                        \
    do {                                                                       \
        As[st][acol + 0][arow0] = pa0.x;                                       \
        As[st][acol + 1][arow0] = pa0.y;                                       \
        As[st][acol + 2][arow0] = pa0.z;                                       \
        As[st][acol + 3][arow0] = pa0.w;                                       \
        As[st][acol + 0][arow1] = pa1.x;                                       \
        As[st][acol + 1][arow1] = pa1.y;                                       \
        As[st][acol + 2][arow1] = pa1.z;                                       \
        As[st][acol + 3][arow1] = pa1.w;                                       \
        *(float4*)&Bs[st][brow0][bcol] = pb0;                                  \
        *(float4*)&Bs[st][brow1][bcol] = pb1;                                  \
    } while (0)

__global__ void __launch_bounds__(256)
gemm_kernel(const float* __restrict__ A, const float* __restrict__ B, int M) {
    __shared__ __align__(16) float As[2][BK][BMP];
    __shared__ __align__(16) float Bs[2][BK][BN];

    const int tid = threadIdx.x;
    const int bm  = blockIdx.x * BM;
    const int bn  = blockIdx.y * BN;
    const int tx  = tid & 15;
    const int ty  = tid >> 4;

    const int arow0 = tid >> 2;
    const int arow1 = arow0 + 64;
    const int acol  = (tid & 3) << 2;
    const int brow0 = tid >> 5;
    const int brow1 = brow0 + 8;
    const int bcol  = (tid & 31) << 2;

    const float4 zero4 = make_float4(0.f, 0.f, 0.f, 0.f);
    float4 pa0, pa1, pb0, pb1;

    // packed accumulators: acc2[i][j] holds {col 2j, col 2j+1} for row i
    unsigned long long acc2[8][4];
    #pragma unroll
    for (int i = 0; i < 8; i++)
        #pragma unroll
        for (int j = 0; j < 4; j++) acc2[i][j] = 0ull;

    GEMM_LOADG(0);
    GEMM_STORES(0);
    __syncthreads();

    int s = 0;
    for (int k0 = 0; k0 < IN_DIM; k0 += BK) {
        const bool more = (k0 + BK) < IN_DIM;
        if (more) GEMM_LOADG(k0 + BK);

        #pragma unroll
        for (int kk = 0; kk < BK; kk++) {
            float4 a0 = *(const float4*)&As[s][kk][ty * 4];
            float4 a1 = *(const float4*)&As[s][kk][ty * 4 + 64];
            unsigned long long bv[4];
            bv[0] = *(const unsigned long long*)&Bs[s][kk][tx * 4];
            bv[1] = *(const unsigned long long*)&Bs[s][kk][tx * 4 + 2];
            bv[2] = *(const unsigned long long*)&Bs[s][kk][tx * 4 + 64];
            bv[3] = *(const unsigned long long*)&Bs[s][kk][tx * 4 + 66];
            float av[8] = {a0.x, a0.y, a0.z, a0.w, a1.x, a1.y, a1.z, a1.w};
            #pragma unroll
            for (int i = 0; i < 8; i++) {
                unsigned long long aa;
                asm("mov.b64 %0, {%1, %1};"
                    : "=l"(aa) : "r"(__float_as_uint(av[i])));
                #pragma unroll
                for (int j = 0; j < 4; j++)
                    asm("fma.rn.f32x2 %0, %1, %2, %3;"
                        : "=l"(acc2[i][j])
                        : "l"(aa), "l"(bv[j]), "l"(acc2[i][j]));
            }
        }
        if (more) GEMM_STORES(s ^ 1);
        __syncthreads();
        s ^= 1;
    }

    #pragma unroll
    for (int i = 0; i < 8; i++) {
        int gm = bm + ty * 4 + ((i < 4) ? i : 60 + i);   // i>=4 -> +64+(i-4)
        if (gm < M) {
            float* orow = g_h + (size_t)gm * FDIM + bn + tx * 4;
            #pragma unroll
            for (int jh = 0; jh < 2; jh++) {
                unsigned lo0, hi0, lo1, hi1;
                asm("mov.b64 {%0, %1}, %2;"
                    : "=r"(lo0), "=r"(hi0) : "l"(acc2[i][jh * 2]));
                asm("mov.b64 {%0, %1}, %2;"
                    : "=r"(lo1), "=r"(hi1) : "l"(acc2[i][jh * 2 + 1]));
                *(float4*)(orow + jh * 64) =
                    make_float4(__uint_as_float(lo0), __uint_as_float(hi0),
                                __uint_as_float(lo1), __uint_as_float(hi1));
            }
        }
    }
}

// -------------------- 6. attention dots: warp per node -----------------------
__global__ void attn_kernel(const float* __restrict__ att_src,
                            const float* __restrict__ att_dst, int n) {
    int warp = (blockIdx.x * blockDim.x + threadIdx.x) >> 5;
    int lane = threadIdx.x & 31;
    if (warp >= n) return;

    int head = lane >> 3;
    int off  = (lane & 7) * 8;
    const float* hrow = g_h + (size_t)warp * FDIM + lane * 8;
    const float* asv  = att_src + head * OUT_DIM + off;
    const float* adv  = att_dst + head * OUT_DIM + off;

    float4 v0 = *(const float4*)(hrow);
    float4 v1 = *(const float4*)(hrow + 4);
    float4 a0 = *(const float4*)(asv);
    float4 a1 = *(const float4*)(asv + 4);
    float4 d0 = *(const float4*)(adv);
    float4 d1 = *(const float4*)(adv + 4);

    float ss = v0.x*a0.x + v0.y*a0.y + v0.z*a0.z + v0.w*a0.w
             + v1.x*a1.x + v1.y*a1.y + v1.z*a1.z + v1.w*a1.w;
    float dd = v0.x*d0.x + v0.y*d0.y + v0.z*d0.z + v0.w*d0.w
             + v1.x*d1.x + v1.y*d1.y + v1.z*d1.z + v1.w*d1.w;

    #pragma unroll
    for (int o = 4; o > 0; o >>= 1) {
        ss += __shfl_down_sync(0xffffffffu, ss, o);
        dd += __shfl_down_sync(0xffffffffu, dd, o);
    }
    if ((lane & 7) == 0) {
        g_as[warp * HEADS + head] = ss;
        g_ad[warp * HEADS + head] = dd;
    }
}

// -------------------- 7. aggregation: warp per dst node ----------------------
__global__ void aggregate_kernel(const float* __restrict__ bias,
                                 float* __restrict__ out, int n) {
    int node = (blockIdx.x * blockDim.x + threadIdx.x) >> 5;
    int lane = threadIdx.x & 31;
    if (node >= n) return;

    int beg = g_rowptr[node];
    int end = g_rowptr[node + 1];
    const int h1 = lane >> 4;
    const int h2 = 2 + (lane >> 4);
    const float ad1 = g_ad[node * HEADS + h1];
    const float ad2 = g_ad[node * HEADS + h2];

    float m1 = -CUDART_INF_F, m2 = -CUDART_INF_F;
    float d1 = 0.f, d2 = 0.f;
    float4 acc1 = make_float4(0.f, 0.f, 0.f, 0.f);
    float4 acc2 = make_float4(0.f, 0.f, 0.f, 0.f);

    for (int p = beg; p < end; p++) {
        int s = g_esrc[p];
        float as1 = g_as[s * HEADS + h1];
        float as2 = g_as[s * HEADS + h2];
        float e1 = as1 + ad1; e1 = (e1 > 0.f) ? e1 : NEG_SLOPE * e1;
        float e2 = as2 + ad2; e2 = (e2 > 0.f) ? e2 : NEG_SLOPE * e2;

        float nm1 = fmaxf(m1, e1);
        float nm2 = fmaxf(m2, e2);
        float sc1 = __expf(m1 - nm1);
        float sc2 = __expf(m2 - nm2);
        float w1  = __expf(e1 - nm1);
        float w2  = __expf(e2 - nm2);
        m1 = nm1; m2 = nm2;
        d1 = d1 * sc1 + w1;
        d2 = d2 * sc2 + w2;

        const float* hb = g_h + (size_t)s * FDIM + lane * 4;
        float4 hv1 = *(const float4*)(hb);
        float4 hv2 = *(const float4*)(hb + 128);

        acc1.x = acc1.x * sc1 + w1 * hv1.x;
        acc1.y = acc1.y * sc1 + w1 * hv1.y;
        acc1.z = acc1.z * sc1 + w1 * hv1.z;
        acc1.w = acc1.w * sc1 + w1 * hv1.w;
        acc2.x = acc2.x * sc2 + w2 * hv2.x;
        acc2.y = acc2.y * sc2 + w2 * hv2.y;
        acc2.z = acc2.z * sc2 + w2 * hv2.z;
        acc2.w = acc2.w * sc2 + w2 * hv2.w;
    }

    float inv1 = 1.f / (d1 + 1e-16f);
    float inv2 = 1.f / (d2 + 1e-16f);
    int f1 = lane * 4;
    int f2 = 128 + lane * 4;
    float4 b1 = *(const float4*)(bias + f1);
    float4 b2 = *(const float4*)(bias + f2);

    float4 o1, o2;
    o1.x = fmaxf(acc1.x * inv1 + b1.x, 0.f);
    o1.y = fmaxf(acc1.y * inv1 + b1.y, 0.f);
    o1.z = fmaxf(acc1.z * inv1 + b1.z, 0.f);
    o1.w = fmaxf(acc1.w * inv1 + b1.w, 0.f);
    o2.x = fmaxf(acc2.x * inv2 + b2.x, 0.f);
    o2.y = fmaxf(acc2.y * inv2 + b2.y, 0.f);
    o2.z = fmaxf(acc2.z * inv2 + b2.z, 0.f);
    o2.w = fmaxf(acc2.w * inv2 + b2.w, 0.f);

    float* orow = out + (size_t)node * FDIM;
    *(float4*)(orow + f1) = o1;
    *(float4*)(orow + f2) = o2;
}

// ---------------------------------------------------------------------------
extern "C" void kernel_launch(void* const* d_in, const int* in_sizes, int n_in,
                              void* d_out, int out_size) {
    const float* x       = (const float*)d_in[0];
    const int*   ew      = (const int*)d_in[1];   // raw 32-bit view of edge_index
    const float* W       = (const float*)d_in[2];
    const float* att_src = (const float*)d_in[3];
    const float* att_dst = (const float*)d_in[4];
    const float* bias    = (const float*)d_in[5];
    float*       out     = (float*)d_out;

    int N = in_sizes[0] / IN_DIM;   // 50000
    int E = in_sizes[1] / 2;        // 800000
    int nblk = (N + SCAN_BLK - 1) / SCAN_BLK;

    // CSR build (parallel decoupled scan)
    detect_kernel<<<1, 256>>>(ew, E);
    init_deg_kernel<<<(N + 255) / 256, 256>>>(N);
    count_kernel<<<(E + 255) / 256, 256>>>(ew, E, N);
    partial_kernel<<<nblk, SCAN_BLK>>>(N);
    bsum_scan_kernel<<<1, 256>>>(nblk, N);
    emit_kernel<<<nblk, SCAN_BLK>>>(N);
    scatter_kernel<<<(E + 255) / 256, 256>>>(ew, E, N);

    // projection + attention dots
    dim3 ggrid((N + BM - 1) / BM, FDIM / BN);
    gemm_kernel<<<ggrid, 256>>>(x, W, N);
    attn_kernel<<<((N * 32) + 255) / 256, 256>>>(att_src, att_dst, N);

    // softmax-aggregate
    aggregate_kernel<<<((N * 32) + 255) / 256, 256>>>(bias, out, N);
}

// round 11
// speedup vs baseline: 1.6383x; 1.1395x over previous
#include <cuda_runtime.h>
#include <cuda_bf16.h>
#include <math_constants.h>
#include <cstdint>

// ---------------------------------------------------------------------------
// GAT layer: out = relu( segment_softmax_aggregate( leaky_relu(a_s[j]+a_d[i]),
//                                                   h[j] ) + bias )
// h = x @ W, self loops added, softmax over incoming edges per dst node.
//
// Pipeline (graph-capturable fork-join, allocation-free):
//   side stream:  detect -> init_deg -> count -> partial/bsum/emit -> scatter
//   main stream:  gemm (fp32 f32x2-packed, attention dots fused in epilogue)
//   join:         aggregate (warp per dst node, online softmax over CSR)
// ---------------------------------------------------------------------------

#define N_NODES_MAX 50000
#define N_EDGES_MAX 800000
#define E_TOT_MAX   (N_EDGES_MAX + N_NODES_MAX)
#define IN_DIM  256
#define OUT_DIM 64
#define HEADS   4
#define FDIM    (HEADS * OUT_DIM)   // 256
#define NEG_SLOPE 0.2f
#define SCAN_BLK 256

// -------------------- scratch (static device arrays, 16B aligned) ----------
__device__ __align__(16) float g_h [(size_t)N_NODES_MAX * FDIM];
__device__ float g_as[(size_t)N_NODES_MAX * HEADS];
__device__ float g_ad[(size_t)N_NODES_MAX * HEADS];
__device__ int   g_deg[N_NODES_MAX];
__device__ int   g_rowptr[N_NODES_MAX + 1];
__device__ int   g_pos[N_NODES_MAX];
__device__ int   g_esrc[E_TOT_MAX];
__device__ int   g_bsum[1024];
__device__ int   g_boff[1024];
__device__ int   g_idx64;

// decode edge-index element i from a raw 32-bit view, honoring dtype flag
__device__ __forceinline__ int edge_at(const int* __restrict__ w, int i,
                                       int is64, int n) {
    int v = is64 ? w[2 * i] : w[i];   // int64 ids < 2^31: low word suffices
    v = (v < 0) ? 0 : v;
    return (v >= n) ? (n - 1) : v;    // clamp: degrade, never trap
}

// -------------------- 0. dtype sniff ----------------------------------------
__global__ void detect_kernel(const int* __restrict__ w, int e) {
    __shared__ int nz;
    if (threadIdx.x == 0) nz = 0;
    __syncthreads();
    int pairs = min(e, 2048);
    int bad = 0;
    for (int i = threadIdx.x; i < pairs; i += blockDim.x)
        if (w[2 * i + 1] != 0) bad++;
    if (bad) atomicAdd(&nz, bad);
    __syncthreads();
    if (threadIdx.x == 0) g_idx64 = (nz == 0) ? 1 : 0;
}

// -------------------- 1. init degrees ---------------------------------------
__global__ void init_deg_kernel(int n) {
    int i = blockIdx.x * blockDim.x + threadIdx.x;
    if (i < n) g_deg[i] = 1;
}

// -------------------- 2. count incoming edges --------------------------------
__global__ void count_kernel(const int* __restrict__ w, int e, int n) {
    int i = blockIdx.x * blockDim.x + threadIdx.x;
    if (i >= e) return;
    atomicAdd(&g_deg[edge_at(w, e + i, g_idx64, n)], 1);
}

// -------------------- 3a. per-block degree sums ------------------------------
__global__ void partial_kernel(int n) {
    int i = blockIdx.x * blockDim.x + threadIdx.x;
    int lane = threadIdx.x & 31, wid = threadIdx.x >> 5;
    int v = (i < n) ? g_deg[i] : 0;
    #pragma unroll
    for (int o = 16; o > 0; o >>= 1) v += __shfl_down_sync(0xffffffffu, v, o);
    __shared__ int ws[8];
    if (lane == 0) ws[wid] = v;
    __syncthreads();
    if (wid == 0) {
        int t = (lane < 8) ? ws[lane] : 0;
        #pragma unroll
        for (int o = 4; o > 0; o >>= 1) t += __shfl_down_sync(0xffffffffu, t, o);
        if (lane == 0) g_bsum[blockIdx.x] = t;
    }
}

// -------------------- 3b. scan of block sums ---------------------------------
__global__ void bsum_scan_kernel(int nblk, int n) {
    int t = threadIdx.x, lane = t & 31, wid = t >> 5;
    int v = (t < nblk) ? g_bsum[t] : 0;
    int s = v;
    #pragma unroll
    for (int o = 1; o < 32; o <<= 1) {
        int u = __shfl_up_sync(0xffffffffu, v, o);
        if (lane >= o) v += u;
    }
    __shared__ int ws[8];
    if (lane == 31) ws[wid] = v;
    __syncthreads();
    if (wid == 0 && lane < 8) {
        int w = ws[lane], vw = w;
        #pragma unroll
        for (int o = 1; o < 8; o <<= 1) {
            int u = __shfl_up_sync(0xffu, vw, o);
            if (lane >= o) vw += u;
        }
        ws[lane] = vw - w;
    }
    __syncthreads();
    int excl = ws[wid] + (v - s);
    if (t < nblk) g_boff[t] = excl;
    if (t == nblk - 1) g_rowptr[n] = excl + s;
}

// -------------------- 3c. emit rowptr / self-loop / pos ----------------------
__global__ void emit_kernel(int n) {
    int i = blockIdx.x * blockDim.x + threadIdx.x;
    int lane = threadIdx.x & 31, wid = threadIdx.x >> 5;
    int d = (i < n) ? g_deg[i] : 0;
    int v = d;
    #pragma unroll
    for (int o = 1; o < 32; o <<= 1) {
        int u = __shfl_up_sync(0xffffffffu, v, o);
        if (lane >= o) v += u;
    }
    __shared__ int ws[8];
    if (lane == 31) ws[wid] = v;
    __syncthreads();
    if (wid == 0 && lane < 8) {
        int w = ws[lane], vw = w;
        #pragma unroll
        for (int o = 1; o < 8; o <<= 1) {
            int u = __shfl_up_sync(0xffu, vw, o);
            if (lane >= o) vw += u;
        }
        ws[lane] = vw - w;
    }
    __syncthreads();
    if (i < n) {
        int acc = g_boff[blockIdx.x] + ws[wid] + (v - d);
        g_rowptr[i] = acc;
        g_esrc[acc] = i;             // self loop first (deterministic slot)
        g_pos[i]    = acc + 1;
    }
}

// -------------------- 4. scatter edges into CSR ------------------------------
__global__ void scatter_kernel(const int* __restrict__ w, int e, int n) {
    int i = blockIdx.x * blockDim.x + threadIdx.x;
    if (i >= e) return;
    int is64 = g_idx64;
    int srow = edge_at(w, i,     is64, n);
    int d    = edge_at(w, e + i, is64, n);
    int p = atomicAdd(&g_pos[d], 1);
    g_esrc[p] = srow;
}

// -------------------- 5. SGEMM + fused attn dots -----------------------------
#define BM 128
#define BN 128
#define BK 16
#define BMP 132   // padded row (528 B, multiple of 16 B)

#define GEMM_LOADG(k0)                                                         \
    do {                                                                       \
        int ga0 = bm + arow0, ga1 = bm + arow1;                                \
        pa0 = (ga0 < M) ? *(const float4*)(A + (size_t)ga0 * IN_DIM + (k0) + acol) : zero4; \
        pa1 = (ga1 < M) ? *(const float4*)(A + (size_t)ga1 * IN_DIM + (k0) + acol) : zero4; \
        pb0 = *(const float4*)(B + (size_t)((k0) + brow0) * FDIM + bn + bcol); \
        pb1 = *(const float4*)(B + (size_t)((k0) + brow1) * FDIM + bn + bcol); \
    } while (0)

#define GEMM_STORES(st)                                                        \
    do {                                                                       \
        As[st][acol + 0][arow0] = pa0.x;                                       \
        As[st][acol + 1][arow0] = pa0.y;                                       \
        As[st][acol + 2][arow0] = pa0.z;                                       \
        As[st][acol + 3][arow0] = pa0.w;                                       \
        As[st][acol + 0][arow1] = pa1.x;                                       \
        As[st][acol + 1][arow1] = pa1.y;                                       \
        As[st][acol + 2][arow1] = pa1.z;                                       \
        As[st][acol + 3][arow1] = pa1.w;                                       \
        *(float4*)&Bs[st][brow0][bcol] = pb0;                                  \
        *(float4*)&Bs[st][brow1][bcol] = pb1;                                  \
    } while (0)

__global__ void __launch_bounds__(256, 2)
gemm_kernel(const float* __restrict__ A, const float* __restrict__ B,
            const float* __restrict__ att_src,
            const float* __restrict__ att_dst, int M) {
    __shared__ __align__(16) float As[2][BK][BMP];
    __shared__ __align__(16) float Bs[2][BK][BN];

    const int tid = threadIdx.x;
    const int bm  = blockIdx.x * BM;
    const int by  = blockIdx.y;            // N-tile: heads {2*by, 2*by+1}
    const int bn  = by * BN;
    const int tx  = tid & 15;
    const int ty  = tid >> 4;

    const int arow0 = tid >> 2;
    const int arow1 = arow0 + 64;
    const int acol  = (tid & 3) << 2;
    const int brow0 = tid >> 5;
    const int brow1 = brow0 + 8;
    const int bcol  = (tid & 31) << 2;

    const float4 zero4 = make_float4(0.f, 0.f, 0.f, 0.f);
    float4 pa0, pa1, pb0, pb1;

    // packed accumulators: acc2[i][j] holds {col 2j, col 2j+1} for row i
    unsigned long long acc2[8][4];
    #pragma unroll
    for (int i = 0; i < 8; i++)
        #pragma unroll
        for (int j = 0; j < 4; j++) acc2[i][j] = 0ull;

    GEMM_LOADG(0);
    GEMM_STORES(0);
    __syncthreads();

    int s = 0;
    for (int k0 = 0; k0 < IN_DIM; k0 += BK) {
        const bool more = (k0 + BK) < IN_DIM;
        if (more) GEMM_LOADG(k0 + BK);

        #pragma unroll
        for (int kk = 0; kk < BK; kk++) {
            float4 a0 = *(const float4*)&As[s][kk][ty * 4];
            float4 a1 = *(const float4*)&As[s][kk][ty * 4 + 64];
            unsigned long long bv[4];
            bv[0] = *(const unsigned long long*)&Bs[s][kk][tx * 4];
            bv[1] = *(const unsigned long long*)&Bs[s][kk][tx * 4 + 2];
            bv[2] = *(const unsigned long long*)&Bs[s][kk][tx * 4 + 64];
            bv[3] = *(const unsigned long long*)&Bs[s][kk][tx * 4 + 66];
            float av[8] = {a0.x, a0.y, a0.z, a0.w, a1.x, a1.y, a1.z, a1.w};
            #pragma unroll
            for (int i = 0; i < 8; i++) {
                unsigned long long aa;
                asm("mov.b64 %0, {%1, %1};"
                    : "=l"(aa) : "r"(__float_as_uint(av[i])));
                #pragma unroll
                for (int j = 0; j < 4; j++)
                    asm("fma.rn.f32x2 %0, %1, %2, %3;"
                        : "=l"(acc2[i][j])
                        : "l"(aa), "l"(bv[j]), "l"(acc2[i][j]));
            }
        }
        if (more) GEMM_STORES(s ^ 1);
        __syncthreads();
        s ^= 1;
    }

    // att vector slices for this thread's columns (row-invariant)
    const int hA = by * 2, hB = by * 2 + 1;
    float4 vsA = *(const float4*)(att_src + hA * OUT_DIM + tx * 4);
    float4 vdA = *(const float4*)(att_dst + hA * OUT_DIM + tx * 4);
    float4 vsB = *(const float4*)(att_src + hB * OUT_DIM + tx * 4);
    float4 vdB = *(const float4*)(att_dst + hB * OUT_DIM + tx * 4);

    #pragma unroll
    for (int i = 0; i < 8; i++) {
        int gm = bm + ty * 4 + ((i < 4) ? i : 60 + i);   // i>=4 -> +64+(i-4)
        unsigned lo0, hi0, lo1, hi1, lo2, hi2, lo3, hi3;
        asm("mov.b64 {%0, %1}, %2;" : "=r"(lo0), "=r"(hi0) : "l"(acc2[i][0]));
        asm("mov.b64 {%0, %1}, %2;" : "=r"(lo1), "=r"(hi1) : "l"(acc2[i][1]));
        asm("mov.b64 {%0, %1}, %2;" : "=r"(lo2), "=r"(hi2) : "l"(acc2[i][2]));
        asm("mov.b64 {%0, %1}, %2;" : "=r"(lo3), "=r"(hi3) : "l"(acc2[i][3]));
        float f0 = __uint_as_float(lo0), f1 = __uint_as_float(hi0);
        float f2 = __uint_as_float(lo1), f3 = __uint_as_float(hi1);
        float f4 = __uint_as_float(lo2), f5 = __uint_as_float(hi2);
        float f6 = __uint_as_float(lo3), f7 = __uint_as_float(hi3);

        if (gm < M) {
            float* orow = g_h + (size_t)gm * FDIM + bn + tx * 4;
            *(float4*)(orow)      = make_float4(f0, f1, f2, f3);
            *(float4*)(orow + 64) = make_float4(f4, f5, f6, f7);
        }

        // fused attention dots: partial over this thread's 4 cols per head
        float ssA = f0*vsA.x + f1*vsA.y + f2*vsA.z + f3*vsA.w;
        float ddA = f0*vdA.x + f1*vdA.y + f2*vdA.z + f3*vdA.w;
        float ssB = f4*vsB.x + f5*vsB.y + f6*vsB.z + f7*vsB.w;
        float ddB = f4*vdB.x + f5*vdB.y + f6*vdB.z + f7*vdB.w;
        #pragma unroll
        for (int m = 1; m <= 8; m <<= 1) {
            ssA += __shfl_xor_sync(0xffffffffu, ssA, m);
            ddA += __shfl_xor_sync(0xffffffffu, ddA, m);
            ssB += __shfl_xor_sync(0xffffffffu, ssB, m);
            ddB += __shfl_xor_sync(0xffffffffu, ddB, m);
        }
        if (tx == 0 && gm < M) {
            g_as[gm * HEADS + hA] = ssA;
            g_ad[gm * HEADS + hA] = ddA;
            g_as[gm * HEADS + hB] = ssB;
            g_ad[gm * HEADS + hB] = ddB;
        }
    }
}

// -------------------- 6. aggregation: warp per dst node ----------------------
__global__ void aggregate_kernel(const float* __restrict__ bias,
                                 float* __restrict__ out, int n) {
    int node = (blockIdx.x * blockDim.x + threadIdx.x) >> 5;
    int lane = threadIdx.x & 31;
    if (node >= n) return;

    int beg = g_rowptr[node];
    int end = g_rowptr[node + 1];
    const int h1 = lane >> 4;
    const int h2 = 2 + (lane >> 4);
    const float ad1 = g_ad[node * HEADS + h1];
    const float ad2 = g_ad[node * HEADS + h2];

    float m1 = -CUDART_INF_F, m2 = -CUDART_INF_F;
    float d1 = 0.f, d2 = 0.f;
    float4 acc1 = make_float4(0.f, 0.f, 0.f, 0.f);
    float4 acc2 = make_float4(0.f, 0.f, 0.f, 0.f);

    for (int p = beg; p < end; p++) {
        int s = g_esrc[p];
        float as1 = g_as[s * HEADS + h1];
        float as2 = g_as[s * HEADS + h2];
        float e1 = as1 + ad1; e1 = (e1 > 0.f) ? e1 : NEG_SLOPE * e1;
        float e2 = as2 + ad2; e2 = (e2 > 0.f) ? e2 : NEG_SLOPE * e2;

        float nm1 = fmaxf(m1, e1);
        float nm2 = fmaxf(m2, e2);
        float sc1 = __expf(m1 - nm1);
        float sc2 = __expf(m2 - nm2);
        float w1  = __expf(e1 - nm1);
        float w2  = __expf(e2 - nm2);
        m1 = nm1; m2 = nm2;
        d1 = d1 * sc1 + w1;
        d2 = d2 * sc2 + w2;

        const float* hb = g_h + (size_t)s * FDIM + lane * 4;
        float4 hv1 = *(const float4*)(hb);
        float4 hv2 = *(const float4*)(hb + 128);

        acc1.x = acc1.x * sc1 + w1 * hv1.x;
        acc1.y = acc1.y * sc1 + w1 * hv1.y;
        acc1.z = acc1.z * sc1 + w1 * hv1.z;
        acc1.w = acc1.w * sc1 + w1 * hv1.w;
        acc2.x = acc2.x * sc2 + w2 * hv2.x;
        acc2.y = acc2.y * sc2 + w2 * hv2.y;
        acc2.z = acc2.z * sc2 + w2 * hv2.z;
        acc2.w = acc2.w * sc2 + w2 * hv2.w;
    }

    float inv1 = 1.f / (d1 + 1e-16f);
    float inv2 = 1.f / (d2 + 1e-16f);
    int f1 = lane * 4;
    int f2 = 128 + lane * 4;
    float4 b1 = *(const float4*)(bias + f1);
    float4 b2 = *(const float4*)(bias + f2);

    float4 o1, o2;
    o1.x = fmaxf(acc1.x * inv1 + b1.x, 0.f);
    o1.y = fmaxf(acc1.y * inv1 + b1.y, 0.f);
    o1.z = fmaxf(acc1.z * inv1 + b1.z, 0.f);
    o1.w = fmaxf(acc1.w * inv1 + b1.w, 0.f);
    o2.x = fmaxf(acc2.x * inv2 + b2.x, 0.f);
    o2.y = fmaxf(acc2.y * inv2 + b2.y, 0.f);
    o2.z = fmaxf(acc2.z * inv2 + b2.z, 0.f);
    o2.w = fmaxf(acc2.w * inv2 + b2.w, 0.f);

    float* orow = out + (size_t)node * FDIM;
    *(float4*)(orow + f1) = o1;
    *(float4*)(orow + f2) = o2;
}

// ---------------------------------------------------------------------------
extern "C" void kernel_launch(void* const* d_in, const int* in_sizes, int n_in,
                              void* d_out, int out_size) {
    const float* x       = (const float*)d_in[0];
    const int*   ew      = (const int*)d_in[1];   // raw 32-bit view of edge_index
    const float* W       = (const float*)d_in[2];
    const float* att_src = (const float*)d_in[3];
    const float* att_dst = (const float*)d_in[4];
    const float* bias    = (const float*)d_in[5];
    float*       out     = (float*)d_out;

    int N = in_sizes[0] / IN_DIM;   // 50000
    int E = in_sizes[1] / 2;        // 800000
    int nblk = (N + SCAN_BLK - 1) / SCAN_BLK;

    // one-time infra init (first call is the uncaptured correctness run)
    static cudaStream_t s_side = 0;
    static cudaEvent_t  ev_fork = 0, ev_join = 0;
    if (!s_side) {
        cudaStreamCreateWithFlags(&s_side, cudaStreamNonBlocking);
        cudaEventCreateWithFlags(&ev_fork, cudaEventDisableTiming);
        cudaEventCreateWithFlags(&ev_join, cudaEventDisableTiming);
    }

    // fork: CSR build runs on side stream, concurrent with the GEMM
    cudaEventRecord(ev_fork, 0);
    cudaStreamWaitEvent(s_side, ev_fork, 0);

    detect_kernel  <<<1, 256, 0, s_side>>>(ew, E);
    init_deg_kernel<<<(N + 255) / 256, 256, 0, s_side>>>(N);
    count_kernel   <<<(E + 255) / 256, 256, 0, s_side>>>(ew, E, N);
    partial_kernel <<<nblk, SCAN_BLK, 0, s_side>>>(N);
    bsum_scan_kernel<<<1, 256, 0, s_side>>>(nblk, N);
    emit_kernel    <<<nblk, SCAN_BLK, 0, s_side>>>(N);
    scatter_kernel <<<(E + 255) / 256, 256, 0, s_side>>>(ew, E, N);
    cudaEventRecord(ev_join, s_side);

    // main stream: projection with fused attention dots
    dim3 ggrid((N + BM - 1) / BM, FDIM / BN);
    gemm_kernel<<<ggrid, 256>>>(x, W, att_src, att_dst, N);

    // join, then softmax-aggregate
    cudaStreamWaitEvent(0, ev_join, 0);
    aggregate_kernel<<<((N * 32) + 255) / 256, 256>>>(bias, out, N);
}

// round 12
// speedup vs baseline: 1.9835x; 1.2107x over previous
#include <cuda_runtime.h>
#include <cuda_bf16.h>
#include <math_constants.h>
#include <cstdint>

// ---------------------------------------------------------------------------
// GAT layer, HMMA (mma.sync bf16) edition.
//   h = x@W via 3-pass bf16 hi/lo split on mma.sync.m16n8k16 (base PTX, works
//   on compute_103 where tcgen05 does not), attention dots fused in epilogue.
//   CSR build overlapped on a side stream; warp-per-node online-softmax agg.
// ---------------------------------------------------------------------------

#define N_NODES_MAX 50000
#define M_PAD_MAX   50048                 // ceil(50000/128)*128
#define N_EDGES_MAX 800000
#define E_TOT_MAX   (N_EDGES_MAX + N_NODES_MAX)
#define IN_DIM  256
#define OUT_DIM 64
#define HEADS   4
#define FDIM    (HEADS * OUT_DIM)         // 256
#define NEG_SLOPE 0.2f
#define SCAN_BLK 256

// -------------------- scratch (static device arrays) ------------------------
__device__ __align__(16) float g_h [(size_t)N_NODES_MAX * FDIM];
__device__ float g_as[(size_t)N_NODES_MAX * HEADS];
__device__ float g_ad[(size_t)N_NODES_MAX * HEADS];
__device__ int   g_deg[N_NODES_MAX];
__device__ int   g_rowptr[N_NODES_MAX + 1];
__device__ int   g_pos[N_NODES_MAX];
__device__ int   g_esrc[E_TOT_MAX];
__device__ int   g_bsum[1024];
__device__ int   g_boff[1024];
__device__ int   g_idx64;
__device__ __align__(16) __nv_bfloat16 g_xhi[(size_t)M_PAD_MAX * IN_DIM];
__device__ __align__(16) __nv_bfloat16 g_xlo[(size_t)M_PAD_MAX * IN_DIM];
__device__ __align__(16) __nv_bfloat16 g_bhi[FDIM * IN_DIM];   // [n][k] = W[k][n]
__device__ __align__(16) __nv_bfloat16 g_blo[FDIM * IN_DIM];

__device__ __forceinline__ uint32_t smem_to_u32(const void* p) {
    uint32_t a;
    asm("{ .reg .u64 t; cvta.to.shared.u64 t, %1; cvt.u32.u64 %0, t; }"
        : "=r"(a) : "l"(p));
    return a;
}

// pack two bf16 into bf162 without extra rounding
__device__ __forceinline__ __nv_bfloat162 pack_bf162(__nv_bfloat16 a,
                                                     __nv_bfloat16 b) {
    __nv_bfloat162 r; r.x = a; r.y = b; return r;
}

// decode edge-index element (handles int32/int64 harness conventions)
__device__ __forceinline__ int edge_at(const int* __restrict__ w, int i,
                                       int is64, int n) {
    int v = is64 ? w[2 * i] : w[i];
    v = (v < 0) ? 0 : v;
    return (v >= n) ? (n - 1) : v;
}

// ==================== prep: hi/lo split of x and W^T =========================
__global__ void prep_x_kernel(const float* __restrict__ x, int mpad, int nreal) {
    int i = blockIdx.x * blockDim.x + threadIdx.x;      // one float4 per thread
    if (i >= mpad * (IN_DIM / 4)) return;
    int row = i >> 6;
    int c4  = (i & 63) << 2;
    float4 v = make_float4(0.f, 0.f, 0.f, 0.f);
    if (row < nreal) v = *(const float4*)(x + (size_t)row * IN_DIM + c4);
    __nv_bfloat16 h0 = __float2bfloat16(v.x), h1 = __float2bfloat16(v.y);
    __nv_bfloat16 h2 = __float2bfloat16(v.z), h3 = __float2bfloat16(v.w);
    float l0 = v.x - __bfloat162float(h0), l1 = v.y - __bfloat162float(h1);
    float l2 = v.z - __bfloat162float(h2), l3 = v.w - __bfloat162float(h3);
    size_t o = (size_t)row * IN_DIM + c4;
    *(__nv_bfloat162*)(g_xhi + o)     = pack_bf162(h0, h1);
    *(__nv_bfloat162*)(g_xhi + o + 2) = pack_bf162(h2, h3);
    *(__nv_bfloat162*)(g_xlo + o)     = __floats2bfloat162_rn(l0, l1);
    *(__nv_bfloat162*)(g_xlo + o + 2) = __floats2bfloat162_rn(l2, l3);
}

__global__ void prep_w_kernel(const float* __restrict__ W) {
    int i = blockIdx.x * blockDim.x + threadIdx.x;      // over 256*256
    if (i >= FDIM * IN_DIM) return;
    int n = i >> 8, k = i & 255;
    float w = W[(size_t)k * FDIM + n];
    __nv_bfloat16 h = __float2bfloat16(w);
    g_bhi[(size_t)n * IN_DIM + k] = h;
    g_blo[(size_t)n * IN_DIM + k] = __float2bfloat16(w - __bfloat162float(h));
}

// ==================== HMMA GEMM: h = x@W, fused attn dots ====================
// CTA tile 128x128, 8 warps (4 x-m, 2 x-n), warp tile 32x64 (one head in N).
// Per chunk: k=32 slice of one of 3 passes (xhi*Whi, xhi*Wlo, xlo*Whi).
// SMEM: double-buffered 128x32 bf16 tiles, row pitch 40 bf16 (80 B) ->
// conflict-free ldmatrix (20-word stride, 8 rows hit distinct banks).
#define PITCH_BF 40
#define TILE_SM  (128 * PITCH_BF)        // bf16 elems per tile buffer
#define NCHUNK   24                       // 3 passes x 8 k-chunks of 32

__global__ void __launch_bounds__(256)
gemm_mma_kernel(const float* __restrict__ att_src,
                const float* __restrict__ att_dst, int M) {
    __shared__ __align__(16) __nv_bfloat16 sA[2][TILE_SM];
    __shared__ __align__(16) __nv_bfloat16 sB[2][TILE_SM];

    const int tid   = threadIdx.x;
    const int lane  = tid & 31;
    const int warp  = tid >> 5;
    const int wm    = warp & 3;            // warp m index (0..3)
    const int wn    = warp >> 2;           // warp n index (0..1)
    const int bm    = blockIdx.x * 128;
    const int by    = blockIdx.y;          // N-tile: heads {2*by, 2*by+1}
    const int bn    = by * 128;

    const uint32_t sA_u32 = smem_to_u32(sA);
    const uint32_t sB_u32 = smem_to_u32(sB);

    // loader plan: 2 uint4 per thread per tile (512 units of 16B per tile)
    const int lrow = tid >> 2;             // 0..63 (+64 for u=1)
    const int lkq  = tid & 3;              // 16B quarter within 32-k row

    float acc[2][8][4];
    #pragma unroll
    for (int a = 0; a < 2; a++)
        #pragma unroll
        for (int b = 0; b < 8; b++)
            #pragma unroll
            for (int c = 0; c < 4; c++) acc[a][b][c] = 0.f;

    uint4 pa[2], pb[2];
    const __nv_bfloat16* aseg;
    const __nv_bfloat16* bseg;

    // ---- preload chunk 0
    aseg = g_xhi; bseg = g_bhi;
    #pragma unroll
    for (int u = 0; u < 2; u++) {
        int row = lrow + u * 64;
        pa[u] = *(const uint4*)(aseg + (size_t)(bm + row) * IN_DIM + lkq * 8);
        pb[u] = *(const uint4*)(bseg + (size_t)(bn + row) * IN_DIM + lkq * 8);
    }
    #pragma unroll
    for (int u = 0; u < 2; u++) {
        int row = lrow + u * 64;
        *(uint4*)((char*)sA[0] + row * 80 + lkq * 16) = pa[u];
        *(uint4*)((char*)sB[0] + row * 80 + lkq * 16) = pb[u];
    }
    __syncthreads();

    int s = 0;
    for (int c = 0; c < NCHUNK; c++) {
        const bool more = (c + 1) < NCHUNK;
        if (more) {
            const int cn   = c + 1;
            const int pass = cn >> 3;                 // 0,1,2
            const int kc   = (cn & 7) << 5;           // 0..224
            aseg = (pass < 2) ? g_xhi : g_xlo;
            bseg = (pass == 1) ? g_blo : g_bhi;
            #pragma unroll
            for (int u = 0; u < 2; u++) {
                int row = lrow + u * 64;
                pa[u] = *(const uint4*)(aseg + (size_t)(bm + row) * IN_DIM + kc + lkq * 8);
                pb[u] = *(const uint4*)(bseg + (size_t)(bn + row) * IN_DIM + kc + lkq * 8);
            }
        }

        const uint32_t abase = sA_u32 + s * (TILE_SM * 2);
        const uint32_t bbase = sB_u32 + s * (TILE_SM * 2);

        #pragma unroll
        for (int kk2 = 0; kk2 < 2; kk2++) {
            const int kko = kk2 * 16;
            uint32_t af[2][4], bf[4][4];
            // A fragments: m16k16 tiles at rows wm*32 + tm*16
            #pragma unroll
            for (int tm = 0; tm < 2; tm++) {
                uint32_t addr = abase
                    + (uint32_t)(wm * 32 + tm * 16 + ((lane >> 3) & 1) * 8 + (lane & 7)) * 80u
                    + (uint32_t)(kko + (lane >> 4) * 8) * 2u;
                asm volatile(
                    "ldmatrix.sync.aligned.m8n8.x4.shared.b16 {%0,%1,%2,%3}, [%4];"
                    : "=r"(af[tm][0]), "=r"(af[tm][1]),
                      "=r"(af[tm][2]), "=r"(af[tm][3]) : "r"(addr));
            }
            // B fragments: each x4 covers two n8 tiles (k16 each)
            #pragma unroll
            for (int p = 0; p < 4; p++) {
                uint32_t addr = bbase
                    + (uint32_t)(wn * 64 + p * 16 + (lane >> 4) * 8 + (lane & 7)) * 80u
                    + (uint32_t)(kko + ((lane >> 3) & 1) * 8) * 2u;
                asm volatile(
                    "ldmatrix.sync.aligned.m8n8.x4.shared.b16 {%0,%1,%2,%3}, [%4];"
                    : "=r"(bf[p][0]), "=r"(bf[p][1]),
                      "=r"(bf[p][2]), "=r"(bf[p][3]) : "r"(addr));
            }
            #pragma unroll
            for (int tm = 0; tm < 2; tm++)
                #pragma unroll
                for (int p = 0; p < 4; p++) {
                    asm volatile(
                        "mma.sync.aligned.m16n8k16.row.col.f32.bf16.bf16.f32 "
                        "{%0,%1,%2,%3}, {%4,%5,%6,%7}, {%8,%9}, {%0,%1,%2,%3};"
                        : "+f"(acc[tm][2*p][0]), "+f"(acc[tm][2*p][1]),
                          "+f"(acc[tm][2*p][2]), "+f"(acc[tm][2*p][3])
                        : "r"(af[tm][0]), "r"(af[tm][1]),
                          "r"(af[tm][2]), "r"(af[tm][3]),
                          "r"(bf[p][0]), "r"(bf[p][1]));
                    asm volatile(
                        "mma.sync.aligned.m16n8k16.row.col.f32.bf16.bf16.f32 "
                        "{%0,%1,%2,%3}, {%4,%5,%6,%7}, {%8,%9}, {%0,%1,%2,%3};"
                        : "+f"(acc[tm][2*p+1][0]), "+f"(acc[tm][2*p+1][1]),
                          "+f"(acc[tm][2*p+1][2]), "+f"(acc[tm][2*p+1][3])
                        : "r"(af[tm][0]), "r"(af[tm][1]),
                          "r"(af[tm][2]), "r"(af[tm][3]),
                          "r"(bf[p][2]), "r"(bf[p][3]));
                }
        }

        if (more) {
            #pragma unroll
            for (int u = 0; u < 2; u++) {
                int row = lrow + u * 64;
                *(uint4*)((char*)sA[s ^ 1] + row * 80 + lkq * 16) = pa[u];
                *(uint4*)((char*)sB[s ^ 1] + row * 80 + lkq * 16) = pb[u];
            }
        }
        __syncthreads();
        s ^= 1;
    }

    // ---- epilogue: store h, fused attention dots (warp tile = one head) ----
    const int h = by * 2 + wn;
    const float* asv = att_src + h * OUT_DIM;
    const float* adv = att_dst + h * OUT_DIM;
    const int q  = lane & 3;
    const int r4 = lane >> 2;

    #pragma unroll
    for (int tm = 0; tm < 2; tm++) {
        #pragma unroll
        for (int half = 0; half < 2; half++) {
            int gm = bm + wm * 32 + tm * 16 + half * 8 + r4;
            float ss = 0.f, dd = 0.f;
            float* orow = g_h + (size_t)gm * FDIM + h * OUT_DIM;
            #pragma unroll
            for (int nt = 0; nt < 8; nt++) {
                float d0 = acc[tm][nt][half * 2];
                float d1 = acc[tm][nt][half * 2 + 1];
                int cc = nt * 8 + q * 2;
                if (gm < M) {
                    float2 v; v.x = d0; v.y = d1;
                    *(float2*)(orow + cc) = v;
                }
                ss = fmaf(d0, asv[cc], ss); ss = fmaf(d1, asv[cc + 1], ss);
                dd = fmaf(d0, adv[cc], dd); dd = fmaf(d1, adv[cc + 1], dd);
            }
            ss += __shfl_xor_sync(0xffffffffu, ss, 1);
            ss += __shfl_xor_sync(0xffffffffu, ss, 2);
            dd += __shfl_xor_sync(0xffffffffu, dd, 1);
            dd += __shfl_xor_sync(0xffffffffu, dd, 2);
            if (q == 0 && gm < M) {
                g_as[gm * HEADS + h] = ss;
                g_ad[gm * HEADS + h] = dd;
            }
        }
    }
}

// ==================== CSR build (proven, overlapped) =========================
__global__ void detect_kernel(const int* __restrict__ w, int e) {
    __shared__ int nz;
    if (threadIdx.x == 0) nz = 0;
    __syncthreads();
    int pairs = min(e, 2048);
    int bad = 0;
    for (int i = threadIdx.x; i < pairs; i += blockDim.x)
        if (w[2 * i + 1] != 0) bad++;
    if (bad) atomicAdd(&nz, bad);
    __syncthreads();
    if (threadIdx.x == 0) g_idx64 = (nz == 0) ? 1 : 0;
}

__global__ void init_deg_kernel(int n) {
    int i = blockIdx.x * blockDim.x + threadIdx.x;
    if (i < n) g_deg[i] = 1;
}

__global__ void count_kernel(const int* __restrict__ w, int e, int n) {
    int i = blockIdx.x * blockDim.x + threadIdx.x;
    if (i >= e) return;
    atomicAdd(&g_deg[edge_at(w, e + i, g_idx64, n)], 1);
}

__global__ void partial_kernel(int n) {
    int i = blockIdx.x * blockDim.x + threadIdx.x;
    int lane = threadIdx.x & 31, wid = threadIdx.x >> 5;
    int v = (i < n) ? g_deg[i] : 0;
    #pragma unroll
    for (int o = 16; o > 0; o >>= 1) v += __shfl_down_sync(0xffffffffu, v, o);
    __shared__ int ws[8];
    if (lane == 0) ws[wid] = v;
    __syncthreads();
    if (wid == 0) {
        int t = (lane < 8) ? ws[lane] : 0;
        #pragma unroll
        for (int o = 4; o > 0; o >>= 1) t += __shfl_down_sync(0xffffffffu, t, o);
        if (lane == 0) g_bsum[blockIdx.x] = t;
    }
}

__global__ void bsum_scan_kernel(int nblk, int n) {
    int t = threadIdx.x, lane = t & 31, wid = t >> 5;
    int v = (t < nblk) ? g_bsum[t] : 0;
    int s = v;
    #pragma unroll
    for (int o = 1; o < 32; o <<= 1) {
        int u = __shfl_up_sync(0xffffffffu, v, o);
        if (lane >= o) v += u;
    }
    __shared__ int ws[8];
    if (lane == 31) ws[wid] = v;
    __syncthreads();
    if (wid == 0 && lane < 8) {
        int w = ws[lane], vw = w;
        #pragma unroll
        for (int o = 1; o < 8; o <<= 1) {
            int u = __shfl_up_sync(0xffu, vw, o);
            if (lane >= o) vw += u;
        }
        ws[lane] = vw - w;
    }
    __syncthreads();
    int excl = ws[wid] + (v - s);
    if (t < nblk) g_boff[t] = excl;
    if (t == nblk - 1) g_rowptr[n] = excl + s;
}

__global__ void emit_kernel(int n) {
    int i = blockIdx.x * blockDim.x + threadIdx.x;
    int lane = threadIdx.x & 31, wid = threadIdx.x >> 5;
    int d = (i < n) ? g_deg[i] : 0;
    int v = d;
    #pragma unroll
    for (int o = 1; o < 32; o <<= 1) {
        int u = __shfl_up_sync(0xffffffffu, v, o);
        if (lane >= o) v += u;
    }
    __shared__ int ws[8];
    if (lane == 31) ws[wid] = v;
    __syncthreads();
    if (wid == 0 && lane < 8) {
        int w = ws[lane], vw = w;
        #pragma unroll
        for (int o = 1; o < 8; o <<= 1) {
            int u = __shfl_up_sync(0xffu, vw, o);
            if (lane >= o) vw += u;
        }
        ws[lane] = vw - w;
    }
    __syncthreads();
    if (i < n) {
        int acc = g_boff[blockIdx.x] + ws[wid] + (v - d);
        g_rowptr[i] = acc;
        g_esrc[acc] = i;             // self loop first (deterministic slot)
        g_pos[i]    = acc + 1;
    }
}

__global__ void scatter_kernel(const int* __restrict__ w, int e, int n) {
    int i = blockIdx.x * blockDim.x + threadIdx.x;
    if (i >= e) return;
    int is64 = g_idx64;
    int srow = edge_at(w, i,     is64, n);
    int d    = edge_at(w, e + i, is64, n);
    int p = atomicAdd(&g_pos[d], 1);
    g_esrc[p] = srow;
}

// ==================== aggregation: warp per dst node =========================
__global__ void aggregate_kernel(const float* __restrict__ bias,
                                 float* __restrict__ out, int n) {
    int node = (blockIdx.x * blockDim.x + threadIdx.x) >> 5;
    int lane = threadIdx.x & 31;
    if (node >= n) return;

    int beg = g_rowptr[node];
    int end = g_rowptr[node + 1];
    const int h1 = lane >> 4;
    const int h2 = 2 + (lane >> 4);
    const float ad1 = g_ad[node * HEADS + h1];
    const float ad2 = g_ad[node * HEADS + h2];

    float m1 = -CUDART_INF_F, m2 = -CUDART_INF_F;
    float d1 = 0.f, d2 = 0.f;
    float4 acc1 = make_float4(0.f, 0.f, 0.f, 0.f);
    float4 acc2 = make_float4(0.f, 0.f, 0.f, 0.f);

    for (int p = beg; p < end; p++) {
        int s = g_esrc[p];
        float as1 = g_as[s * HEADS + h1];
        float as2 = g_as[s * HEADS + h2];
        float e1 = as1 + ad1; e1 = (e1 > 0.f) ? e1 : NEG_SLOPE * e1;
        float e2 = as2 + ad2; e2 = (e2 > 0.f) ? e2 : NEG_SLOPE * e2;

        float nm1 = fmaxf(m1, e1);
        float nm2 = fmaxf(m2, e2);
        float sc1 = __expf(m1 - nm1);
        float sc2 = __expf(m2 - nm2);
        float w1  = __expf(e1 - nm1);
        float w2  = __expf(e2 - nm2);
        m1 = nm1; m2 = nm2;
        d1 = d1 * sc1 + w1;
        d2 = d2 * sc2 + w2;

        const float* hb = g_h + (size_t)s * FDIM + lane * 4;
        float4 hv1 = *(const float4*)(hb);
        float4 hv2 = *(const float4*)(hb + 128);

        acc1.x = acc1.x * sc1 + w1 * hv1.x;
        acc1.y = acc1.y * sc1 + w1 * hv1.y;
        acc1.z = acc1.z * sc1 + w1 * hv1.z;
        acc1.w = acc1.w * sc1 + w1 * hv1.w;
        acc2.x = acc2.x * sc2 + w2 * hv2.x;
        acc2.y = acc2.y * sc2 + w2 * hv2.y;
        acc2.z = acc2.z * sc2 + w2 * hv2.z;
        acc2.w = acc2.w * sc2 + w2 * hv2.w;
    }

    float inv1 = 1.f / (d1 + 1e-16f);
    float inv2 = 1.f / (d2 + 1e-16f);
    int f1 = lane * 4;
    int f2 = 128 + lane * 4;
    float4 b1 = *(const float4*)(bias + f1);
    float4 b2 = *(const float4*)(bias + f2);

    float4 o1, o2;
    o1.x = fmaxf(acc1.x * inv1 + b1.x, 0.f);
    o1.y = fmaxf(acc1.y * inv1 + b1.y, 0.f);
    o1.z = fmaxf(acc1.z * inv1 + b1.z, 0.f);
    o1.w = fmaxf(acc1.w * inv1 + b1.w, 0.f);
    o2.x = fmaxf(acc2.x * inv2 + b2.x, 0.f);
    o2.y = fmaxf(acc2.y * inv2 + b2.y, 0.f);
    o2.z = fmaxf(acc2.z * inv2 + b2.z, 0.f);
    o2.w = fmaxf(acc2.w * inv2 + b2.w, 0.f);

    float* orow = out + (size_t)node * FDIM;
    *(float4*)(orow + f1) = o1;
    *(float4*)(orow + f2) = o2;
}

// ---------------------------------------------------------------------------
extern "C" void kernel_launch(void* const* d_in, const int* in_sizes, int n_in,
                              void* d_out, int out_size) {
    const float* x       = (const float*)d_in[0];
    const int*   ew      = (const int*)d_in[1];   // raw 32-bit view of edge_index
    const float* W       = (const float*)d_in[2];
    const float* att_src = (const float*)d_in[3];
    const float* att_dst = (const float*)d_in[4];
    const float* bias    = (const float*)d_in[5];
    float*       out     = (float*)d_out;

    int N = in_sizes[0] / IN_DIM;   // 50000
    int E = in_sizes[1] / 2;        // 800000
    int mtiles = (N + 127) / 128;   // 391
    int mpad   = mtiles * 128;      // 50048
    int nblk   = (N + SCAN_BLK - 1) / SCAN_BLK;

    // one-time infra init (first call is the uncaptured correctness run)
    static cudaStream_t s_side = 0;
    static cudaEvent_t  ev_fork = 0, ev_join = 0;
    if (!s_side) {
        cudaStreamCreateWithFlags(&s_side, cudaStreamNonBlocking);
        cudaEventCreateWithFlags(&ev_fork, cudaEventDisableTiming);
        cudaEventCreateWithFlags(&ev_join, cudaEventDisableTiming);
    }

    // fork: CSR build runs on side stream, concurrent with prep + GEMM
    cudaEventRecord(ev_fork, 0);
    cudaStreamWaitEvent(s_side, ev_fork, 0);

    detect_kernel   <<<1, 256, 0, s_side>>>(ew, E);
    init_deg_kernel <<<(N + 255) / 256, 256, 0, s_side>>>(N);
    count_kernel    <<<(E + 255) / 256, 256, 0, s_side>>>(ew, E, N);
    partial_kernel  <<<nblk, SCAN_BLK, 0, s_side>>>(N);
    bsum_scan_kernel<<<1, 256, 0, s_side>>>(nblk, N);
    emit_kernel     <<<nblk, SCAN_BLK, 0, s_side>>>(N);
    scatter_kernel  <<<(E + 255) / 256, 256, 0, s_side>>>(ew, E, N);
    cudaEventRecord(ev_join, s_side);

    // main stream: hi/lo prep, then HMMA projection with fused attn dots
    prep_x_kernel<<<(mpad * 64 + 255) / 256, 256>>>(x, mpad, N);
    prep_w_kernel<<<(FDIM * IN_DIM + 255) / 256, 256>>>(W);
    {
        dim3 g(mtiles, 2);
        gemm_mma_kernel<<<g, 256>>>(att_src, att_dst, N);
    }

    // join, then softmax-aggregate
    cudaStreamWaitEvent(0, ev_join, 0);
    aggregate_kernel<<<((N * 32) + 255) / 256, 256>>>(bias, out, N);
}